// round 14
// baseline (speedup 1.0000x reference)
#include <cuda_runtime.h>

constexpr int B_   = 2;
constexpr int SQ_  = 2048;
constexpr int SKV_ = 2048;
constexpr int H_   = 1024;
constexpr int NH_  = 16;
constexpr int HD_  = 64;

__device__ float g_q[(size_t)B_ * SQ_ * H_];
__device__ float g_k[(size_t)B_ * SKV_ * H_];
__device__ float g_v[(size_t)B_ * SKV_ * H_];
__device__ float g_ctx[(size_t)B_ * SQ_ * H_];

__device__ __forceinline__ unsigned f2tf(float f) {
    unsigned u; asm("cvt.rna.tf32.f32 %0, %1;" : "=r"(u) : "f"(f)); return u;
}
__device__ __forceinline__ void mma8(float d[4], const unsigned a[4], const unsigned b[2]) {
    asm volatile(
        "mma.sync.aligned.m16n8k8.row.col.f32.tf32.tf32.f32 "
        "{%0,%1,%2,%3},{%4,%5,%6,%7},{%8,%9},{%0,%1,%2,%3};"
        : "+f"(d[0]), "+f"(d[1]), "+f"(d[2]), "+f"(d[3])
        : "r"(a[0]), "r"(a[1]), "r"(a[2]), "r"(a[3]), "r"(b[0]), "r"(b[1]));
}
__device__ __forceinline__ uint4 pack_tf(float4 v) {
    return make_uint4(f2tf(v.x), f2tf(v.y), f2tf(v.z), f2tf(v.w));
}

// ---------------- projection GEMM v2: 4 warps, warp tile 64x64 -------------
// 128x128 CTA tile, BK=16 double-buffered. 32 independent mmas per warp per
// k-slice (2x the ILP of the 8-warp version), 1.0 LDS per mma.
__device__ __forceinline__ void gemm_body(
    const float* __restrict__ A, const float* __restrict__ W,
    const float* __restrict__ bias, float* __restrict__ C,
    int M, int N, int K)
{
    __shared__ __align__(16) unsigned As[2][128][20];
    __shared__ __align__(16) unsigned Bs[2][128][20];

    const int tid = threadIdx.x;
    const int wid = tid >> 5, lane = tid & 31;
    const int g = lane >> 2, tg = lane & 3;
    const int wm = wid >> 1, wn = wid & 1;          // 2 x 2 warp grid
    const int m0 = blockIdx.y << 7, n0 = blockIdx.x << 7;
    const int lrow = tid;                            // 0..127: one row per thread

    const float* Ap = A + (size_t)(m0 + lrow) * K;
    const float* Wp = W + (size_t)(n0 + lrow) * K;

    float acc[4][8][4] = {};
    float4 av[4], wv[4];
    #pragma unroll
    for (int i = 0; i < 4; i++) {
        av[i] = *(const float4*)(Ap + (i << 2));
        wv[i] = *(const float4*)(Wp + (i << 2));
    }
    {
        *(uint4*)&As[0][lrow][0]  = pack_tf(av[0]);
        *(uint4*)&As[0][lrow][4]  = pack_tf(av[1]);
        *(uint4*)&As[0][lrow][8]  = pack_tf(av[2]);
        *(uint4*)&As[0][lrow][12] = pack_tf(av[3]);
        *(uint4*)&Bs[0][lrow][0]  = pack_tf(wv[0]);
        *(uint4*)&Bs[0][lrow][4]  = pack_tf(wv[1]);
        *(uint4*)&Bs[0][lrow][8]  = pack_tf(wv[2]);
        *(uint4*)&Bs[0][lrow][12] = pack_tf(wv[3]);
    }
    __syncthreads();

    const int NT = K >> 4;
    for (int kt = 0; kt < NT; kt++) {
        if (kt + 1 < NT) {
            const float* Ap2 = Ap + (kt + 1) * 16;
            const float* Wp2 = Wp + (kt + 1) * 16;
            #pragma unroll
            for (int i = 0; i < 4; i++) {
                av[i] = *(const float4*)(Ap2 + (i << 2));
                wv[i] = *(const float4*)(Wp2 + (i << 2));
            }
        }
        const int buf = kt & 1;
        #pragma unroll
        for (int ks = 0; ks < 2; ks++) {
            const int kk = ks << 3;
            unsigned bfr[8][2];
            #pragma unroll
            for (int ni = 0; ni < 8; ni++) {
                const int col = (wn << 6) + (ni << 3) + g;
                bfr[ni][0] = Bs[buf][col][kk + tg];
                bfr[ni][1] = Bs[buf][col][kk + tg + 4];
            }
            #pragma unroll
            for (int mi = 0; mi < 4; mi++) {
                const int row = (wm << 6) + (mi << 4);
                unsigned af[4];
                af[0] = As[buf][row + g    ][kk + tg];
                af[1] = As[buf][row + g + 8][kk + tg];
                af[2] = As[buf][row + g    ][kk + tg + 4];
                af[3] = As[buf][row + g + 8][kk + tg + 4];
                #pragma unroll
                for (int ni = 0; ni < 8; ni++) mma8(acc[mi][ni], af, bfr[ni]);
            }
        }
        if (kt + 1 < NT) {
            *(uint4*)&As[buf ^ 1][lrow][0]  = pack_tf(av[0]);
            *(uint4*)&As[buf ^ 1][lrow][4]  = pack_tf(av[1]);
            *(uint4*)&As[buf ^ 1][lrow][8]  = pack_tf(av[2]);
            *(uint4*)&As[buf ^ 1][lrow][12] = pack_tf(av[3]);
            *(uint4*)&Bs[buf ^ 1][lrow][0]  = pack_tf(wv[0]);
            *(uint4*)&Bs[buf ^ 1][lrow][4]  = pack_tf(wv[1]);
            *(uint4*)&Bs[buf ^ 1][lrow][8]  = pack_tf(wv[2]);
            *(uint4*)&Bs[buf ^ 1][lrow][12] = pack_tf(wv[3]);
        }
        __syncthreads();
    }

    #pragma unroll
    for (int mi = 0; mi < 4; mi++) {
        const int r = m0 + (wm << 6) + (mi << 4) + g;
        #pragma unroll
        for (int ni = 0; ni < 8; ni++) {
            const int c = n0 + (wn << 6) + (ni << 3) + (tg << 1);
            float bx = 0.f, by = 0.f;
            if (bias) { bx = bias[c]; by = bias[c + 1]; }
            *(float2*)(C + (size_t)r * N + c) =
                make_float2(acc[mi][ni][0] + bx, acc[mi][ni][1] + by);
            *(float2*)(C + (size_t)(r + 8) * N + c) =
                make_float2(acc[mi][ni][2] + bx, acc[mi][ni][3] + by);
        }
    }
}

// One batch's QKV: grid (8, 16, 3); pointers pre-offset to the batch.
__global__ __launch_bounds__(128, 2) void qkv_proj(
    const float* __restrict__ xq, const float* __restrict__ xkv,
    const float* __restrict__ Wq, const float* __restrict__ bq,
    const float* __restrict__ Wk,
    const float* __restrict__ Wv, const float* __restrict__ bv,
    float* __restrict__ q, float* __restrict__ k, float* __restrict__ v)
{
    const int z = blockIdx.z;
    const float* A    = (z == 0) ? xq : xkv;
    const float* W    = (z == 0) ? Wq : (z == 1 ? Wk : Wv);
    const float* bias = (z == 0) ? bq : (z == 1 ? nullptr : bv);
    float* C          = (z == 0) ? q  : (z == 1 ? k  : v);
    gemm_body(A, W, bias, C, SQ_, H_, H_);
}

__global__ __launch_bounds__(128, 2) void out_proj(
    const float* __restrict__ ctx, const float* __restrict__ Wo,
    const float* __restrict__ bo, float* __restrict__ out)
{
    gemm_body(ctx, Wo, bo, out, SQ_, H_, H_);
}

// ---------------------------------------------------------------------------
// Flash v5 (R10-proven, untouched), batch passed as arg; grid (16, 16, 1).
// ---------------------------------------------------------------------------
constexpr int FLASH_SMEM = (128 * 68 + 64 * 68 + 64 * 72 + 8 * 16 * 68) * 4;

__global__ __launch_bounds__(256, 2) void flash_mma5(const float* __restrict__ mask, int b)
{
    extern __shared__ unsigned fsm[];
    unsigned (*Qs)[68] = (unsigned(*)[68])fsm;
    unsigned (*Ks)[68] = (unsigned(*)[68])(fsm + 128 * 68);
    unsigned (*Vs)[72] = (unsigned(*)[72])(fsm + 128 * 68 + 64 * 68);
    unsigned* Pbase = fsm + 128 * 68 + 64 * 68 + 64 * 72;

    const int tid = threadIdx.x, wid = tid >> 5, lane = tid & 31;
    const int g = lane >> 2, tg = lane & 3;
    const int r0 = wid << 4;
    const int q0 = blockIdx.x << 7, h = blockIdx.y;

    const float* Qg = g_q + (size_t)(b * SQ_ + q0) * H_ + h * HD_;
    const float* Kg = g_k + (size_t)b * SKV_ * H_ + h * HD_;
    const float* Vg = g_v + (size_t)b * SKV_ * H_ + h * HD_;
    const float* Mg = mask + (size_t)(b * SQ_ + q0) * SKV_;
    unsigned (*Pw)[68] = (unsigned(*)[68])(Pbase + wid * (16 * 68));

    #pragma unroll
    for (int i = 0; i < 8; i++) {
        const int idx = tid + (i << 8);
        const int r = idx >> 4, d = (idx & 15) << 2;
        const float4 v = *(const float4*)(Qg + (size_t)r * H_ + d);
        *(uint4*)&Qs[r][d] = make_uint4(f2tf(v.x * 0.125f), f2tf(v.y * 0.125f),
                                        f2tf(v.z * 0.125f), f2tf(v.w * 0.125f));
    }

    float4 kr[4], vr[4];
    #pragma unroll
    for (int i = 0; i < 4; i++) {
        const int idx = tid + (i << 8);
        const int c = idx >> 4, d = (idx & 15) << 2;
        kr[i] = *(const float4*)(Kg + (size_t)c * H_ + d);
        vr[i] = *(const float4*)(Vg + (size_t)c * H_ + d);
    }

    float mr0 = -1e30f, mr1 = -1e30f, lr0 = 0.f, lr1 = 0.f;
    float o[8][4] = {};

    for (int kv0 = 0; kv0 < SKV_; kv0 += 64) {
        __syncthreads();
        #pragma unroll
        for (int i = 0; i < 4; i++) {
            const int idx = tid + (i << 8);
            const int c = idx >> 4, d = (idx & 15) << 2;
            *(uint4*)&Ks[c][d] = make_uint4(f2tf(kr[i].x), f2tf(kr[i].y),
                                            f2tf(kr[i].z), f2tf(kr[i].w));
            *(uint4*)&Vs[c][d] = make_uint4(f2tf(vr[i].x), f2tf(vr[i].y),
                                            f2tf(vr[i].z), f2tf(vr[i].w));
        }
        __syncthreads();

        float s[8][4] = {};
        #pragma unroll
        for (int ks = 0; ks < 8; ks++) {
            const int kk = ks << 3;
            unsigned af[4];
            af[0] = Qs[r0 + g    ][kk + tg];
            af[1] = Qs[r0 + g + 8][kk + tg];
            af[2] = Qs[r0 + g    ][kk + tg + 4];
            af[3] = Qs[r0 + g + 8][kk + tg + 4];
            unsigned bf[8][2];
            #pragma unroll
            for (int ni = 0; ni < 8; ni++) {
                const int c = (ni << 3) + g;
                bf[ni][0] = Ks[c][kk + tg];
                bf[ni][1] = Ks[c][kk + tg + 4];
            }
            #pragma unroll
            for (int ni = 0; ni < 8; ni++) mma8(s[ni], af, bf[ni]);
        }

        float tm0 = -1e30f, tm1 = -1e30f;
        #pragma unroll
        for (int ni = 0; ni < 8; ni++) {
            const int c = (ni << 3) + (tg << 1);
            const float2 mv0 = *(const float2*)(Mg + (size_t)(r0 + g) * SKV_ + kv0 + c);
            const float2 mv1 = *(const float2*)(Mg + (size_t)(r0 + g + 8) * SKV_ + kv0 + c);
            s[ni][0] += (mv0.x - 1.f) * 10000.f;
            s[ni][1] += (mv0.y - 1.f) * 10000.f;
            s[ni][2] += (mv1.x - 1.f) * 10000.f;
            s[ni][3] += (mv1.y - 1.f) * 10000.f;
            tm0 = fmaxf(tm0, fmaxf(s[ni][0], s[ni][1]));
            tm1 = fmaxf(tm1, fmaxf(s[ni][2], s[ni][3]));
        }
        tm0 = fmaxf(tm0, __shfl_xor_sync(~0u, tm0, 1));
        tm0 = fmaxf(tm0, __shfl_xor_sync(~0u, tm0, 2));
        tm1 = fmaxf(tm1, __shfl_xor_sync(~0u, tm1, 1));
        tm1 = fmaxf(tm1, __shfl_xor_sync(~0u, tm1, 2));

        const float mn0 = fmaxf(mr0, tm0), mn1 = fmaxf(mr1, tm1);
        const float al0 = __expf(mr0 - mn0), al1 = __expf(mr1 - mn1);
        mr0 = mn0; mr1 = mn1;

        float ps0 = 0.f, ps1 = 0.f;
        #pragma unroll
        for (int ni = 0; ni < 8; ni++) {
            const int c = (ni << 3) + (tg << 1);
            const float p00 = __expf(s[ni][0] - mn0), p01 = __expf(s[ni][1] - mn0);
            const float p10 = __expf(s[ni][2] - mn1), p11 = __expf(s[ni][3] - mn1);
            ps0 += p00 + p01; ps1 += p10 + p11;
            Pw[g    ][c] = f2tf(p00); Pw[g    ][c + 1] = f2tf(p01);
            Pw[g + 8][c] = f2tf(p10); Pw[g + 8][c + 1] = f2tf(p11);
            o[ni][0] *= al0; o[ni][1] *= al0; o[ni][2] *= al1; o[ni][3] *= al1;
        }
        ps0 += __shfl_xor_sync(~0u, ps0, 1); ps0 += __shfl_xor_sync(~0u, ps0, 2);
        ps1 += __shfl_xor_sync(~0u, ps1, 1); ps1 += __shfl_xor_sync(~0u, ps1, 2);
        lr0 = lr0 * al0 + ps0;
        lr1 = lr1 * al1 + ps1;

        if (kv0 + 64 < SKV_) {
            #pragma unroll
            for (int i = 0; i < 4; i++) {
                const int idx = tid + (i << 8);
                const int c = idx >> 4, d = (idx & 15) << 2;
                kr[i] = *(const float4*)(Kg + (size_t)(kv0 + 64 + c) * H_ + d);
                vr[i] = *(const float4*)(Vg + (size_t)(kv0 + 64 + c) * H_ + d);
            }
        }
        __syncwarp();

        #pragma unroll
        for (int ks = 0; ks < 8; ks++) {
            const int kk = ks << 3;
            unsigned af[4];
            af[0] = Pw[g    ][kk + tg];
            af[1] = Pw[g + 8][kk + tg];
            af[2] = Pw[g    ][kk + tg + 4];
            af[3] = Pw[g + 8][kk + tg + 4];
            unsigned bf[8][2];
            #pragma unroll
            for (int ni = 0; ni < 8; ni++) {
                const int e = (ni << 3) + g;
                bf[ni][0] = Vs[kk + tg][e];
                bf[ni][1] = Vs[kk + tg + 4][e];
            }
            #pragma unroll
            for (int ni = 0; ni < 8; ni++) mma8(o[ni], af, bf[ni]);
        }
        __syncwarp();
    }

    float* Og = g_ctx + (size_t)(b * SQ_ + q0) * H_ + h * HD_;
    const float inv0 = 1.f / lr0, inv1 = 1.f / lr1;
    #pragma unroll
    for (int ni = 0; ni < 8; ni++) {
        const int c = (ni << 3) + (tg << 1);
        *(float2*)(Og + (size_t)(r0 + g) * H_ + c) =
            make_float2(o[ni][0] * inv0, o[ni][1] * inv0);
        *(float2*)(Og + (size_t)(r0 + g + 8) * H_ + c) =
            make_float2(o[ni][2] * inv1, o[ni][3] * inv1);
    }
}

// ---------------------------------------------------------------------------
// Priority-skewed dual-stream pipeline (R13-proven).
// ---------------------------------------------------------------------------
extern "C" void kernel_launch(void* const* d_in, const int* in_sizes, int n_in,
                              void* d_out, int out_size)
{
    const float* xq  = (const float*)d_in[0];
    const float* xkv = (const float*)d_in[1];
    const float* msk = (const float*)d_in[2];
    const float* Wq  = (const float*)d_in[3];
    const float* bq  = (const float*)d_in[4];
    const float* Wk  = (const float*)d_in[5];
    const float* Wv  = (const float*)d_in[6];
    const float* bv  = (const float*)d_in[7];
    const float* Wo  = (const float*)d_in[8];
    const float* bo  = (const float*)d_in[9];
    float* out = (float*)d_out;

    static cudaStream_t s0 = nullptr, s1 = nullptr;
    static cudaEvent_t evF = nullptr, evJ0 = nullptr, evJ1 = nullptr;
    if (s0 == nullptr) {
        int prLo, prHi;
        cudaDeviceGetStreamPriorityRange(&prLo, &prHi);
        cudaStreamCreateWithPriority(&s0, cudaStreamNonBlocking, prHi);
        cudaStreamCreateWithPriority(&s1, cudaStreamNonBlocking, prLo);
        cudaEventCreateWithFlags(&evF,  cudaEventDisableTiming);
        cudaEventCreateWithFlags(&evJ0, cudaEventDisableTiming);
        cudaEventCreateWithFlags(&evJ1, cudaEventDisableTiming);
        cudaFuncSetAttribute(flash_mma5,
                             cudaFuncAttributeMaxDynamicSharedMemorySize, FLASH_SMEM);
    }

    void *pq, *pk, *pv, *pc;
    cudaGetSymbolAddress(&pq, g_q);
    cudaGetSymbolAddress(&pk, g_k);
    cudaGetSymbolAddress(&pv, g_v);
    cudaGetSymbolAddress(&pc, g_ctx);
    float* q = (float*)pq; float* k = (float*)pk;
    float* v = (float*)pv; float* ctx = (float*)pc;

    constexpr size_t BSTR = (size_t)SQ_ * H_;
    const dim3 blkG(128);       // gemm CTAs are 4 warps now
    const dim3 blkF(256);
    const dim3 gq(8, 16, 3);
    const dim3 gf(16, 16, 1);
    const dim3 go(8, 16);

    cudaEventRecord(evF, 0);
    cudaStreamWaitEvent(s0, evF, 0);
    cudaStreamWaitEvent(s1, evF, 0);

    // s0 (high priority): batch 0 pipeline
    qkv_proj<<<gq, blkG, 0, s0>>>(xq, xkv, Wq, bq, Wk, Wv, bv, q, k, v);
    flash_mma5<<<gf, blkF, FLASH_SMEM, s0>>>(msk, 0);
    out_proj<<<go, blkG, 0, s0>>>(ctx, Wo, bo, out);

    // s1 (low priority): batch 1 pipeline (backfills idle capacity)
    qkv_proj<<<gq, blkG, 0, s1>>>(xq + BSTR, xkv + BSTR, Wq, bq, Wk, Wv, bv,
                                  q + BSTR, k + BSTR, v + BSTR);
    flash_mma5<<<gf, blkF, FLASH_SMEM, s1>>>(msk, 1);
    out_proj<<<go, blkG, 0, s1>>>(ctx + BSTR, Wo, bo, out + BSTR);

    cudaEventRecord(evJ0, s0);
    cudaEventRecord(evJ1, s1);
    cudaStreamWaitEvent(0, evJ0, 0);
    cudaStreamWaitEvent(0, evJ1, 0);
}

// round 17
// speedup vs baseline: 1.2511x; 1.2511x over previous
#include <cuda_runtime.h>
#include <cstdint>

constexpr int B_   = 2;
constexpr int SQ_  = 2048;
constexpr int SKV_ = 2048;
constexpr int H_   = 1024;
constexpr int NH_  = 16;
constexpr int HD_  = 64;

__device__ float g_q[(size_t)B_ * SQ_ * H_];
__device__ float g_k[(size_t)B_ * SKV_ * H_];
__device__ float g_v[(size_t)B_ * SKV_ * H_];
__device__ float g_ctx[(size_t)B_ * SQ_ * H_];

__device__ __forceinline__ unsigned f2tf(float f) {
    unsigned u; asm("cvt.rna.tf32.f32 %0, %1;" : "=r"(u) : "f"(f)); return u;
}
__device__ __forceinline__ void mma8(float d[4], const unsigned a[4], const unsigned b[2]) {
    asm volatile(
        "mma.sync.aligned.m16n8k8.row.col.f32.tf32.tf32.f32 "
        "{%0,%1,%2,%3},{%4,%5,%6,%7},{%8,%9},{%0,%1,%2,%3};"
        : "+f"(d[0]), "+f"(d[1]), "+f"(d[2]), "+f"(d[3])
        : "r"(a[0]), "r"(a[1]), "r"(a[2]), "r"(a[3]), "r"(b[0]), "r"(b[1]));
}
__device__ __forceinline__ void ldsm4(unsigned r[4], uint32_t addr) {
    asm volatile("ldmatrix.sync.aligned.m8n8.x4.shared.b16 {%0,%1,%2,%3}, [%4];"
        : "=r"(r[0]), "=r"(r[1]), "=r"(r[2]), "=r"(r[3]) : "r"(addr));
}
__device__ __forceinline__ uint32_t smem_u32(const void* p) {
    uint32_t a;
    asm("{ .reg .u64 t; cvta.to.shared.u64 t, %1; cvt.u32.u64 %0, t; }" : "=r"(a) : "l"(p));
    return a;
}

// ---------------- projection GEMM (R5 shape + LDSM fragment loads) ---------
// 128x128 tile, BK=16 double-buffered, 256 thr / 8 warps (2x4), warp 64x32.
// Row stride 20 words = 80 B: 16B-aligned, LDSM row banks all distinct.
__device__ __forceinline__ void gemm_body(
    const float* __restrict__ A, const float* __restrict__ W,
    const float* __restrict__ bias, float* __restrict__ C,
    int M, int N, int K)
{
    __shared__ __align__(16) unsigned As[2][128][20];
    __shared__ __align__(16) unsigned Bs[2][128][20];

    const int tid = threadIdx.x;
    const int wid = tid >> 5, lane = tid & 31;
    const int g = lane >> 2, tg = lane & 3;
    const int wm = wid >> 2, wn = wid & 3;
    const int m0 = blockIdx.y << 7, n0 = blockIdx.x << 7;
    const int lrow = tid >> 1;
    const int lk   = (tid & 1) << 3;

    // LDSM per-lane address components
    const int j = lane & 7, quad = lane >> 3;
    const uint32_t aLane = (uint32_t)((j + (quad & 1) * 8) * 80 + (quad >> 1) * 16);
    const uint32_t bLane = (uint32_t)(((quad >> 1) * 8 + j) * 80 + (quad & 1) * 16);
    const uint32_t aBase = smem_u32(&As[0][0][0]) + (uint32_t)(wm << 6) * 80 + aLane;
    const uint32_t bBase = smem_u32(&Bs[0][0][0]) + (uint32_t)(wn << 5) * 80 + bLane;

    const float* Ap = A + (size_t)(m0 + lrow) * K + lk;
    const float* Wp = W + (size_t)(n0 + lrow) * K + lk;

    float acc[4][4][4] = {};
    float4 a0v = *(const float4*)Ap, a1v = *(const float4*)(Ap + 4);
    float4 b0v = *(const float4*)Wp, b1v = *(const float4*)(Wp + 4);
    {
        unsigned* ar = &As[0][lrow][lk];
        ar[0]=f2tf(a0v.x); ar[1]=f2tf(a0v.y); ar[2]=f2tf(a0v.z); ar[3]=f2tf(a0v.w);
        ar[4]=f2tf(a1v.x); ar[5]=f2tf(a1v.y); ar[6]=f2tf(a1v.z); ar[7]=f2tf(a1v.w);
        unsigned* br = &Bs[0][lrow][lk];
        br[0]=f2tf(b0v.x); br[1]=f2tf(b0v.y); br[2]=f2tf(b0v.z); br[3]=f2tf(b0v.w);
        br[4]=f2tf(b1v.x); br[5]=f2tf(b1v.y); br[6]=f2tf(b1v.z); br[7]=f2tf(b1v.w);
    }
    __syncthreads();

    const int NT = K >> 4;
    for (int kt = 0; kt < NT; kt++) {
        if (kt + 1 < NT) {
            const float* Ap2 = Ap + (kt + 1) * 16;
            const float* Wp2 = Wp + (kt + 1) * 16;
            a0v = *(const float4*)Ap2; a1v = *(const float4*)(Ap2 + 4);
            b0v = *(const float4*)Wp2; b1v = *(const float4*)(Wp2 + 4);
        }
        const int buf = kt & 1;
        const uint32_t bufOff = (uint32_t)buf * 10240;   // 128*80
        #pragma unroll
        for (int ks = 0; ks < 2; ks++) {
            const uint32_t kOff = bufOff + (uint32_t)(ks << 5);   // kk*4 bytes
            // B: two LDSM.x4 cover all 4 ni fragment pairs
            unsigned bfr[4][2];
            ldsm4(&bfr[0][0], bBase + kOff);           // ni 0,1
            ldsm4(&bfr[2][0], bBase + kOff + 1280);    // ni 2,3  (16 rows * 80B)
            #pragma unroll
            for (int mi = 0; mi < 4; mi++) {
                unsigned af[4];
                ldsm4(af, aBase + kOff + (uint32_t)mi * 1280);
                #pragma unroll
                for (int ni = 0; ni < 4; ni++) mma8(acc[mi][ni], af, bfr[ni]);
            }
        }
        if (kt + 1 < NT) {
            unsigned* ar = &As[buf ^ 1][lrow][lk];
            ar[0]=f2tf(a0v.x); ar[1]=f2tf(a0v.y); ar[2]=f2tf(a0v.z); ar[3]=f2tf(a0v.w);
            ar[4]=f2tf(a1v.x); ar[5]=f2tf(a1v.y); ar[6]=f2tf(a1v.z); ar[7]=f2tf(a1v.w);
            unsigned* br = &Bs[buf ^ 1][lrow][lk];
            br[0]=f2tf(b0v.x); br[1]=f2tf(b0v.y); br[2]=f2tf(b0v.z); br[3]=f2tf(b0v.w);
            br[4]=f2tf(b1v.x); br[5]=f2tf(b1v.y); br[6]=f2tf(b1v.z); br[7]=f2tf(b1v.w);
        }
        __syncthreads();
    }

    #pragma unroll
    for (int mi = 0; mi < 4; mi++) {
        const int r = m0 + (wm << 6) + (mi << 4) + g;
        #pragma unroll
        for (int ni = 0; ni < 4; ni++) {
            const int c = n0 + (wn << 5) + (ni << 3) + (tg << 1);
            float bx = 0.f, by = 0.f;
            if (bias) { bx = bias[c]; by = bias[c + 1]; }
            *(float2*)(C + (size_t)r * N + c) =
                make_float2(acc[mi][ni][0] + bx, acc[mi][ni][1] + by);
            *(float2*)(C + (size_t)(r + 8) * N + c) =
                make_float2(acc[mi][ni][2] + bx, acc[mi][ni][3] + by);
        }
    }
}

__global__ __launch_bounds__(256) void qkv_proj(
    const float* __restrict__ xq, const float* __restrict__ xkv,
    const float* __restrict__ Wq, const float* __restrict__ bq,
    const float* __restrict__ Wk,
    const float* __restrict__ Wv, const float* __restrict__ bv,
    float* __restrict__ q, float* __restrict__ k, float* __restrict__ v)
{
    const int z = blockIdx.z;
    const float* A    = (z == 0) ? xq : xkv;
    const float* W    = (z == 0) ? Wq : (z == 1 ? Wk : Wv);
    const float* bias = (z == 0) ? bq : (z == 1 ? nullptr : bv);
    float* C          = (z == 0) ? q  : (z == 1 ? k  : v);
    gemm_body(A, W, bias, C, SQ_, H_, H_);
}

__global__ __launch_bounds__(256) void out_proj(
    const float* __restrict__ ctx, const float* __restrict__ Wo,
    const float* __restrict__ bo, float* __restrict__ out)
{
    gemm_body(ctx, Wo, bo, out, SQ_, H_, H_);
}

// ---------------------------------------------------------------------------
// Flash v5 (R10-proven, untouched), batch passed as arg; grid (16, 16, 1).
// ---------------------------------------------------------------------------
constexpr int FLASH_SMEM = (128 * 68 + 64 * 68 + 64 * 72 + 8 * 16 * 68) * 4;

__global__ __launch_bounds__(256, 2) void flash_mma5(const float* __restrict__ mask, int b)
{
    extern __shared__ unsigned fsm[];
    unsigned (*Qs)[68] = (unsigned(*)[68])fsm;
    unsigned (*Ks)[68] = (unsigned(*)[68])(fsm + 128 * 68);
    unsigned (*Vs)[72] = (unsigned(*)[72])(fsm + 128 * 68 + 64 * 68);
    unsigned* Pbase = fsm + 128 * 68 + 64 * 68 + 64 * 72;

    const int tid = threadIdx.x, wid = tid >> 5, lane = tid & 31;
    const int g = lane >> 2, tg = lane & 3;
    const int r0 = wid << 4;
    const int q0 = blockIdx.x << 7, h = blockIdx.y;

    const float* Qg = g_q + (size_t)(b * SQ_ + q0) * H_ + h * HD_;
    const float* Kg = g_k + (size_t)b * SKV_ * H_ + h * HD_;
    const float* Vg = g_v + (size_t)b * SKV_ * H_ + h * HD_;
    const float* Mg = mask + (size_t)(b * SQ_ + q0) * SKV_;
    unsigned (*Pw)[68] = (unsigned(*)[68])(Pbase + wid * (16 * 68));

    #pragma unroll
    for (int i = 0; i < 8; i++) {
        const int idx = tid + (i << 8);
        const int r = idx >> 4, d = (idx & 15) << 2;
        const float4 v = *(const float4*)(Qg + (size_t)r * H_ + d);
        *(uint4*)&Qs[r][d] = make_uint4(f2tf(v.x * 0.125f), f2tf(v.y * 0.125f),
                                        f2tf(v.z * 0.125f), f2tf(v.w * 0.125f));
    }

    float4 kr[4], vr[4];
    #pragma unroll
    for (int i = 0; i < 4; i++) {
        const int idx = tid + (i << 8);
        const int c = idx >> 4, d = (idx & 15) << 2;
        kr[i] = *(const float4*)(Kg + (size_t)c * H_ + d);
        vr[i] = *(const float4*)(Vg + (size_t)c * H_ + d);
    }

    float mr0 = -1e30f, mr1 = -1e30f, lr0 = 0.f, lr1 = 0.f;
    float o[8][4] = {};

    for (int kv0 = 0; kv0 < SKV_; kv0 += 64) {
        __syncthreads();
        #pragma unroll
        for (int i = 0; i < 4; i++) {
            const int idx = tid + (i << 8);
            const int c = idx >> 4, d = (idx & 15) << 2;
            *(uint4*)&Ks[c][d] = make_uint4(f2tf(kr[i].x), f2tf(kr[i].y),
                                            f2tf(kr[i].z), f2tf(kr[i].w));
            *(uint4*)&Vs[c][d] = make_uint4(f2tf(vr[i].x), f2tf(vr[i].y),
                                            f2tf(vr[i].z), f2tf(vr[i].w));
        }
        __syncthreads();

        float s[8][4] = {};
        #pragma unroll
        for (int ks = 0; ks < 8; ks++) {
            const int kk = ks << 3;
            unsigned af[4];
            af[0] = Qs[r0 + g    ][kk + tg];
            af[1] = Qs[r0 + g + 8][kk + tg];
            af[2] = Qs[r0 + g    ][kk + tg + 4];
            af[3] = Qs[r0 + g + 8][kk + tg + 4];
            unsigned bf[8][2];
            #pragma unroll
            for (int ni = 0; ni < 8; ni++) {
                const int c = (ni << 3) + g;
                bf[ni][0] = Ks[c][kk + tg];
                bf[ni][1] = Ks[c][kk + tg + 4];
            }
            #pragma unroll
            for (int ni = 0; ni < 8; ni++) mma8(s[ni], af, bf[ni]);
        }

        float tm0 = -1e30f, tm1 = -1e30f;
        #pragma unroll
        for (int ni = 0; ni < 8; ni++) {
            const int c = (ni << 3) + (tg << 1);
            const float2 mv0 = *(const float2*)(Mg + (size_t)(r0 + g) * SKV_ + kv0 + c);
            const float2 mv1 = *(const float2*)(Mg + (size_t)(r0 + g + 8) * SKV_ + kv0 + c);
            s[ni][0] += (mv0.x - 1.f) * 10000.f;
            s[ni][1] += (mv0.y - 1.f) * 10000.f;
            s[ni][2] += (mv1.x - 1.f) * 10000.f;
            s[ni][3] += (mv1.y - 1.f) * 10000.f;
            tm0 = fmaxf(tm0, fmaxf(s[ni][0], s[ni][1]));
            tm1 = fmaxf(tm1, fmaxf(s[ni][2], s[ni][3]));
        }
        tm0 = fmaxf(tm0, __shfl_xor_sync(~0u, tm0, 1));
        tm0 = fmaxf(tm0, __shfl_xor_sync(~0u, tm0, 2));
        tm1 = fmaxf(tm1, __shfl_xor_sync(~0u, tm1, 1));
        tm1 = fmaxf(tm1, __shfl_xor_sync(~0u, tm1, 2));

        const float mn0 = fmaxf(mr0, tm0), mn1 = fmaxf(mr1, tm1);
        const float al0 = __expf(mr0 - mn0), al1 = __expf(mr1 - mn1);
        mr0 = mn0; mr1 = mn1;

        float ps0 = 0.f, ps1 = 0.f;
        #pragma unroll
        for (int ni = 0; ni < 8; ni++) {
            const int c = (ni << 3) + (tg << 1);
            const float p00 = __expf(s[ni][0] - mn0), p01 = __expf(s[ni][1] - mn0);
            const float p10 = __expf(s[ni][2] - mn1), p11 = __expf(s[ni][3] - mn1);
            ps0 += p00 + p01; ps1 += p10 + p11;
            Pw[g    ][c] = f2tf(p00); Pw[g    ][c + 1] = f2tf(p01);
            Pw[g + 8][c] = f2tf(p10); Pw[g + 8][c + 1] = f2tf(p11);
            o[ni][0] *= al0; o[ni][1] *= al0; o[ni][2] *= al1; o[ni][3] *= al1;
        }
        ps0 += __shfl_xor_sync(~0u, ps0, 1); ps0 += __shfl_xor_sync(~0u, ps0, 2);
        ps1 += __shfl_xor_sync(~0u, ps1, 1); ps1 += __shfl_xor_sync(~0u, ps1, 2);
        lr0 = lr0 * al0 + ps0;
        lr1 = lr1 * al1 + ps1;

        if (kv0 + 64 < SKV_) {
            #pragma unroll
            for (int i = 0; i < 4; i++) {
                const int idx = tid + (i << 8);
                const int c = idx >> 4, d = (idx & 15) << 2;
                kr[i] = *(const float4*)(Kg + (size_t)(kv0 + 64 + c) * H_ + d);
                vr[i] = *(const float4*)(Vg + (size_t)(kv0 + 64 + c) * H_ + d);
            }
        }
        __syncwarp();

        #pragma unroll
        for (int ks = 0; ks < 8; ks++) {
            const int kk = ks << 3;
            unsigned af[4];
            af[0] = Pw[g    ][kk + tg];
            af[1] = Pw[g + 8][kk + tg];
            af[2] = Pw[g    ][kk + tg + 4];
            af[3] = Pw[g + 8][kk + tg + 4];
            unsigned bf[8][2];
            #pragma unroll
            for (int ni = 0; ni < 8; ni++) {
                const int e = (ni << 3) + g;
                bf[ni][0] = Vs[kk + tg][e];
                bf[ni][1] = Vs[kk + tg + 4][e];
            }
            #pragma unroll
            for (int ni = 0; ni < 8; ni++) mma8(o[ni], af, bf[ni]);
        }
        __syncwarp();
    }

    float* Og = g_ctx + (size_t)(b * SQ_ + q0) * H_ + h * HD_;
    const float inv0 = 1.f / lr0, inv1 = 1.f / lr1;
    #pragma unroll
    for (int ni = 0; ni < 8; ni++) {
        const int c = (ni << 3) + (tg << 1);
        *(float2*)(Og + (size_t)(r0 + g) * H_ + c) =
            make_float2(o[ni][0] * inv0, o[ni][1] * inv0);
        *(float2*)(Og + (size_t)(r0 + g + 8) * H_ + c) =
            make_float2(o[ni][2] * inv1, o[ni][3] * inv1);
    }
}

// ---------------------------------------------------------------------------
// Priority-skewed dual-stream pipeline (R13-proven).
// ---------------------------------------------------------------------------
extern "C" void kernel_launch(void* const* d_in, const int* in_sizes, int n_in,
                              void* d_out, int out_size)
{
    const float* xq  = (const float*)d_in[0];
    const float* xkv = (const float*)d_in[1];
    const float* msk = (const float*)d_in[2];
    const float* Wq  = (const float*)d_in[3];
    const float* bq  = (const float*)d_in[4];
    const float* Wk  = (const float*)d_in[5];
    const float* Wv  = (const float*)d_in[6];
    const float* bv  = (const float*)d_in[7];
    const float* Wo  = (const float*)d_in[8];
    const float* bo  = (const float*)d_in[9];
    float* out = (float*)d_out;

    static cudaStream_t s0 = nullptr, s1 = nullptr;
    static cudaEvent_t evF = nullptr, evJ0 = nullptr, evJ1 = nullptr;
    if (s0 == nullptr) {
        int prLo, prHi;
        cudaDeviceGetStreamPriorityRange(&prLo, &prHi);
        cudaStreamCreateWithPriority(&s0, cudaStreamNonBlocking, prHi);
        cudaStreamCreateWithPriority(&s1, cudaStreamNonBlocking, prLo);
        cudaEventCreateWithFlags(&evF,  cudaEventDisableTiming);
        cudaEventCreateWithFlags(&evJ0, cudaEventDisableTiming);
        cudaEventCreateWithFlags(&evJ1, cudaEventDisableTiming);
        cudaFuncSetAttribute(flash_mma5,
                             cudaFuncAttributeMaxDynamicSharedMemorySize, FLASH_SMEM);
    }

    void *pq, *pk, *pv, *pc;
    cudaGetSymbolAddress(&pq, g_q);
    cudaGetSymbolAddress(&pk, g_k);
    cudaGetSymbolAddress(&pv, g_v);
    cudaGetSymbolAddress(&pc, g_ctx);
    float* q = (float*)pq; float* k = (float*)pk;
    float* v = (float*)pv; float* ctx = (float*)pc;

    constexpr size_t BSTR = (size_t)SQ_ * H_;
    const dim3 blk(256);
    const dim3 gq(8, 16, 3);
    const dim3 gf(16, 16, 1);
    const dim3 go(8, 16);

    cudaEventRecord(evF, 0);
    cudaStreamWaitEvent(s0, evF, 0);
    cudaStreamWaitEvent(s1, evF, 0);

    // s0 (high priority): batch 0 pipeline
    qkv_proj<<<gq, blk, 0, s0>>>(xq, xkv, Wq, bq, Wk, Wv, bv, q, k, v);
    flash_mma5<<<gf, blk, FLASH_SMEM, s0>>>(msk, 0);
    out_proj<<<go, blk, 0, s0>>>(ctx, Wo, bo, out);

    // s1 (low priority): batch 1 pipeline (backfills idle capacity)
    qkv_proj<<<gq, blk, 0, s1>>>(xq + BSTR, xkv + BSTR, Wq, bq, Wk, Wv, bv,
                                 q + BSTR, k + BSTR, v + BSTR);
    flash_mma5<<<gf, blk, FLASH_SMEM, s1>>>(msk, 1);
    out_proj<<<go, blk, 0, s1>>>(ctx + BSTR, Wo, bo, out + BSTR);

    cudaEventRecord(evJ0, s0);
    cudaEventRecord(evJ1, s1);
    cudaStreamWaitEvent(0, evJ0, 0);
    cudaStreamWaitEvent(0, evJ1, 0);
}